// round 1
// baseline (speedup 1.0000x reference)
#include <cuda_runtime.h>

#define NATOMS 50000
#define FDIM 128
#define KDIM 64
#define NB 5
#define NRI 3
#define NRF 2

// Scratch (allocation-free rule: __device__ globals)
__device__ float g_xa[NATOMS * FDIM];
__device__ float g_xj[NATOMS * FDIM];
__device__ float g_m [NATOMS * FDIM];
__device__ float g_t [NATOMS * FDIM];

__device__ __forceinline__ float sspf(float x) {
    // shifted softplus: log(0.5*exp(x)+0.5) = softplus(x) - ln2, numerically stable
    return fmaxf(x, 0.0f) + log1pf(expf(-fabsf(x))) - 0.69314718055994530942f;
}

// ---------------------------------------------------------------------------
// Elementwise ssp: out = ssp(in)
// ---------------------------------------------------------------------------
__global__ void ssp_k(const float* __restrict__ in, float* __restrict__ out, int n) {
    int i = blockIdx.x * blockDim.x + threadIdx.x;
    if (i < n) out[i] = sspf(in[i]);
}

// ---------------------------------------------------------------------------
// Fused GEMM: Y = epi( pre(X) @ W + bias ; R, U )
//   PRE=1 : apply ssp to X elements on load
//   EPI=0 : Y = ssp(z)
//   EPI=1 : Y = R + z           (residual add; R may alias Y, same-element only)
//   EPI=2 : Y = U[col]*R + z    (gated skip)
// Shapes: X [M,128], W [128,128], Y [M,128]
// ---------------------------------------------------------------------------
#define BM 128
#define BK 16
#define TM 8
#define TN 8

template <int PRE, int EPI>
__global__ __launch_bounds__(256, 2)
void gemm_k(const float* __restrict__ X, const float* __restrict__ W,
            const float* __restrict__ bias, const float* __restrict__ R,
            const float* __restrict__ U, float* __restrict__ Y, int M)
{
    __shared__ float As[BK][BM];    // transposed A tile: As[k][m]
    __shared__ float Bs[BK][FDIM];  // Bs[k][n]

    const int tid = threadIdx.x;
    const int tx = tid & 15;   // n-dim (16)
    const int ty = tid >> 4;   // m-dim (16)
    const int r0 = blockIdx.x * BM;

    float acc[TM][TN];
#pragma unroll
    for (int i = 0; i < TM; i++)
#pragma unroll
        for (int j = 0; j < TN; j++) acc[i][j] = 0.0f;

    for (int k0 = 0; k0 < FDIM; k0 += BK) {
        // Load A tile: 128 rows x 16 cols = 512 float4, 2 per thread
#pragma unroll
        for (int it = 0; it < 2; it++) {
            int li = tid + it * 256;
            int row = li >> 2;       // 4 float4 per row
            int v = li & 3;
            int grow = r0 + row;
            float4 val;
            if (grow < M) {
                val = *(const float4*)(X + (size_t)grow * FDIM + k0 + v * 4);
            } else {
                val = make_float4(0.f, 0.f, 0.f, 0.f);
            }
            if (PRE) {
                val.x = sspf(val.x); val.y = sspf(val.y);
                val.z = sspf(val.z); val.w = sspf(val.w);
            }
            As[v * 4 + 0][row] = val.x;
            As[v * 4 + 1][row] = val.y;
            As[v * 4 + 2][row] = val.z;
            As[v * 4 + 3][row] = val.w;
        }
        // Load B tile: 16 rows x 128 cols = 512 float4
#pragma unroll
        for (int it = 0; it < 2; it++) {
            int li = tid + it * 256;
            int row = li >> 5;       // 32 float4 per row
            int v = li & 31;
            float4 val = *(const float4*)(W + (size_t)(k0 + row) * FDIM + v * 4);
            *(float4*)&Bs[row][v * 4] = val;
        }
        __syncthreads();

#pragma unroll
        for (int k = 0; k < BK; k++) {
            float a[TM], b[TN];
            *(float4*)&a[0] = *(const float4*)&As[k][ty * TM];
            *(float4*)&a[4] = *(const float4*)&As[k][ty * TM + 4];
            *(float4*)&b[0] = *(const float4*)&Bs[k][tx * TN];
            *(float4*)&b[4] = *(const float4*)&Bs[k][tx * TN + 4];
#pragma unroll
            for (int i = 0; i < TM; i++)
#pragma unroll
                for (int j = 0; j < TN; j++)
                    acc[i][j] = fmaf(a[i], b[j], acc[i][j]);
        }
        __syncthreads();
    }

    // Epilogue
    float bv[TN], uv[TN];
#pragma unroll
    for (int j = 0; j < TN; j++) bv[j] = bias[tx * TN + j];
    if (EPI == 2) {
#pragma unroll
        for (int j = 0; j < TN; j++) uv[j] = U[tx * TN + j];
    }
#pragma unroll
    for (int i = 0; i < TM; i++) {
        int row = r0 + ty * TM + i;
        if (row < M) {
#pragma unroll
            for (int j = 0; j < TN; j++) {
                int col = tx * TN + j;
                float z = acc[i][j] + bv[j];
                float y;
                if (EPI == 0)      y = sspf(z);
                else if (EPI == 1) y = R[(size_t)row * FDIM + col] + z;
                else               y = uv[j] * R[(size_t)row * FDIM + col] + z;
                Y[(size_t)row * FDIM + col] = y;
            }
        }
    }
}

// ---------------------------------------------------------------------------
// Fused message pass:
//   for each pair p: m[idx_i[p], :] += ( (cutoff[p]*rbf[p,:]) @ Wg ) * xj[idx_j[p], :]
// 128 threads = 128 features; Wg column in registers (64 regs/thread).
// idx_i sorted -> register accumulation with atomic flush on segment change.
// ---------------------------------------------------------------------------
#define MSG_T 128
#define MSG_PPB 512
#define MSG_S 8

__global__ __launch_bounds__(MSG_T)
void msg_k(const float* __restrict__ cutoffs, const float* __restrict__ rbfs,
           const int* __restrict__ idx_i, const int* __restrict__ idx_j,
           const float* __restrict__ Wg, const float* __restrict__ xj,
           float* __restrict__ m, int npairs)
{
    __shared__ float desc[MSG_S][KDIM];
    __shared__ int si[MSG_S], sj[MSG_S];

    const int t = threadIdx.x;
    float wg[KDIM];
#pragma unroll
    for (int k = 0; k < KDIM; k++) wg[k] = Wg[k * FDIM + t];

    const int p0 = blockIdx.x * MSG_PPB;
    const int pend = min(p0 + MSG_PPB, npairs);

    float acc = 0.0f;
    int prev = -1;

    for (int base = p0; base < pend; base += MSG_S) {
        int ns = min(MSG_S, pend - base);
        __syncthreads();
        for (int li = t; li < ns * KDIM; li += MSG_T) {
            int s = li >> 6, k = li & 63;
            desc[s][k] = cutoffs[base + s] * rbfs[(size_t)(base + s) * KDIM + k];
        }
        if (t < ns) { si[t] = idx_i[base + t]; sj[t] = idx_j[base + t]; }
        __syncthreads();

        for (int s = 0; s < ns; s++) {
            int i = si[s], j = sj[s];
            if (i != prev) {
                if (prev >= 0) atomicAdd(&m[(size_t)prev * FDIM + t], acc);
                acc = 0.0f;
                prev = i;
            }
            float g = 0.0f;
#pragma unroll
            for (int k = 0; k < KDIM; k++) g = fmaf(desc[s][k], wg[k], g);
            acc = fmaf(g, xj[(size_t)j * FDIM + t], acc);
        }
    }
    if (prev >= 0) atomicAdd(&m[(size_t)prev * FDIM + t], acc);
}

// ---------------------------------------------------------------------------
extern "C" void kernel_launch(void* const* d_in, const int* in_sizes, int n_in,
                              void* d_out, int out_size)
{
    const float* features = (const float*)d_in[0];
    const float* cutoffs  = (const float*)d_in[1];
    const float* rbfs     = (const float*)d_in[2];
    const int*   idx_i    = (const int*)d_in[3];
    const int*   idx_j    = (const int*)d_in[4];
    const float* Wg   = (const float*)d_in[5];
    const float* Wi   = (const float*)d_in[6];
    const float* bi   = (const float*)d_in[7];
    const float* Wj   = (const float*)d_in[8];
    const float* bj   = (const float*)d_in[9];
    const float* Wr1  = (const float*)d_in[10];
    const float* br1  = (const float*)d_in[11];
    const float* Wr2  = (const float*)d_in[12];
    const float* br2  = (const float*)d_in[13];
    const float* Wout = (const float*)d_in[14];
    const float* bout = (const float*)d_in[15];
    const float* u    = (const float*)d_in[16];
    const float* Wf1  = (const float*)d_in[17];
    const float* bf1  = (const float*)d_in[18];
    const float* Wf2  = (const float*)d_in[19];
    const float* bf2  = (const float*)d_in[20];
    const int npairs = in_sizes[1];
    float* out = (float*)d_out;

    float *xa, *xjp, *mp, *tp;
    cudaGetSymbolAddress((void**)&xa,  g_xa);
    cudaGetSymbolAddress((void**)&xjp, g_xj);
    cudaGetSymbolAddress((void**)&mp,  g_m);
    cudaGetSymbolAddress((void**)&tp,  g_t);

    const int gemmGrid = (NATOMS + BM - 1) / BM;
    const int nElem = NATOMS * FDIM;
    const int sspGrid = (nElem + 255) / 256;
    const int msgGrid = (npairs + MSG_PPB - 1) / MSG_PPB;

    const float* x = features;
    for (int b = 0; b < NB; b++) {
        float* xout = out + (size_t)b * NATOMS * FDIM;

        // xa = ssp(x)
        ssp_k<<<sspGrid, 256>>>(x, xa, nElem);
        // m  = xi = ssp(xa @ Wi + bi)
        gemm_k<0, 0><<<gemmGrid, 256>>>(xa, Wi + (size_t)b * FDIM * FDIM,
                                        bi + b * FDIM, nullptr, nullptr, mp, NATOMS);
        // xj = ssp(xa @ Wj + bj)
        gemm_k<0, 0><<<gemmGrid, 256>>>(xa, Wj + (size_t)b * FDIM * FDIM,
                                        bj + b * FDIM, nullptr, nullptr, xjp, NATOMS);
        // m += segment_sum( (desc @ Wg) * xj[idx_j], idx_i )
        msg_k<<<msgGrid, MSG_T>>>(cutoffs, rbfs, idx_i, idx_j,
                                  Wg + (size_t)b * KDIM * FDIM, xjp, mp, npairs);
        // interaction residuals
        for (int r = 0; r < NRI; r++) {
            const float* w1 = Wr1 + (size_t)(b * NRI + r) * FDIM * FDIM;
            const float* c1 = br1 + (size_t)(b * NRI + r) * FDIM;
            const float* w2 = Wr2 + (size_t)(b * NRI + r) * FDIM * FDIM;
            const float* c2 = br2 + (size_t)(b * NRI + r) * FDIM;
            gemm_k<1, 0><<<gemmGrid, 256>>>(mp, w1, c1, nullptr, nullptr, tp, NATOMS);
            gemm_k<0, 1><<<gemmGrid, 256>>>(tp, w2, c2, mp, nullptr, mp, NATOMS);
        }
        // x' = u*x + ssp(m) @ Wout + bout
        gemm_k<1, 2><<<gemmGrid, 256>>>(mp, Wout + (size_t)b * FDIM * FDIM,
                                        bout + b * FDIM, x, u + b * FDIM, xout, NATOMS);
        // feature residuals (in-place on output slab)
        for (int r = 0; r < NRF; r++) {
            const float* w1 = Wf1 + (size_t)(b * NRF + r) * FDIM * FDIM;
            const float* c1 = bf1 + (size_t)(b * NRF + r) * FDIM;
            const float* w2 = Wf2 + (size_t)(b * NRF + r) * FDIM * FDIM;
            const float* c2 = bf2 + (size_t)(b * NRF + r) * FDIM;
            gemm_k<1, 0><<<gemmGrid, 256>>>(xout, w1, c1, nullptr, nullptr, tp, NATOMS);
            gemm_k<0, 1><<<gemmGrid, 256>>>(tp, w2, c2, xout, nullptr, xout, NATOMS);
        }
        x = xout;
    }
}

// round 3
// speedup vs baseline: 1.1281x; 1.1281x over previous
#include <cuda_runtime.h>

#define NATOMS 50000
#define FDIM 128
#define KDIM 64
#define NB 5
#define NRI 3
#define NRF 2

// Scratch (allocation-free rule: __device__ globals)
__device__ float g_xj[NATOMS * FDIM];
__device__ float g_m [NATOMS * FDIM];
__device__ float g_t [NATOMS * FDIM];

__device__ __forceinline__ float sspf(float x) {
    // shifted softplus: log(0.5*exp(x)+0.5) = softplus(x) - ln2, numerically stable
    return fmaxf(x, 0.0f) + log1pf(expf(-fabsf(x))) - 0.69314718055994530942f;
}

// ---- packed f32x2 helpers (sm_100+ only; ptxas never auto-fuses these) ----
__device__ __forceinline__ unsigned long long pack2(float lo, float hi) {
    unsigned long long r;
    asm("mov.b64 %0, {%1,%2};" : "=l"(r) : "f"(lo), "f"(hi));
    return r;
}
__device__ __forceinline__ void unpack2(float& lo, float& hi, unsigned long long v) {
    asm("mov.b64 {%0,%1}, %2;" : "=f"(lo), "=f"(hi) : "l"(v));
}
#define FMA_F32X2(d, a, b) \
    asm("fma.rn.f32x2 %0, %1, %2, %0;" : "+l"(d) : "l"(a), "l"(b))

// ---------------------------------------------------------------------------
// Fused GEMM: Y = epi( pre(X) @ W + bias ; R, U )
//   PRE=1 : apply ssp to X elements on load
//   EPI=0 : Y = ssp(z)
//   EPI=1 : Y = R + z           (residual add)
//   EPI=2 : Y = U[col]*R + z    (gated skip)
// Shapes: X [M,128], W [128,128], Y [M,128]
// ---------------------------------------------------------------------------
#define BM 128
#define BK 16
#define TM 8
#define TN 8

template <int PRE, int EPI>
__global__ __launch_bounds__(256, 2)
void gemm_k(const float* __restrict__ X, const float* __restrict__ W,
            const float* __restrict__ bias, const float* __restrict__ R,
            const float* __restrict__ U, float* __restrict__ Y, int M)
{
    __shared__ __align__(16) float As[BK][BM];    // transposed A tile: As[k][m]
    __shared__ __align__(16) float Bs[BK][FDIM];  // Bs[k][n]

    const int tid = threadIdx.x;
    const int tx = tid & 15;   // n-dim (16)
    const int ty = tid >> 4;   // m-dim (16)
    const int r0 = blockIdx.x * BM;

    // packed accumulators: acc2[i][j2] holds columns (2*j2, 2*j2+1)
    unsigned long long acc2[TM][TN / 2];
#pragma unroll
    for (int i = 0; i < TM; i++)
#pragma unroll
        for (int j = 0; j < TN / 2; j++) acc2[i][j] = 0ull;

    for (int k0 = 0; k0 < FDIM; k0 += BK) {
        // Load A tile: 128 rows x 16 cols = 512 float4, 2 per thread
#pragma unroll
        for (int it = 0; it < 2; it++) {
            int li = tid + it * 256;
            int row = li >> 2;       // 4 float4 per row
            int v = li & 3;
            int grow = r0 + row;
            float4 val;
            if (grow < M) {
                val = *(const float4*)(X + (size_t)grow * FDIM + k0 + v * 4);
            } else {
                val = make_float4(0.f, 0.f, 0.f, 0.f);
            }
            if (PRE) {
                val.x = sspf(val.x); val.y = sspf(val.y);
                val.z = sspf(val.z); val.w = sspf(val.w);
            }
            As[v * 4 + 0][row] = val.x;
            As[v * 4 + 1][row] = val.y;
            As[v * 4 + 2][row] = val.z;
            As[v * 4 + 3][row] = val.w;
        }
        // Load B tile: 16 rows x 128 cols = 512 float4
#pragma unroll
        for (int it = 0; it < 2; it++) {
            int li = tid + it * 256;
            int row = li >> 5;       // 32 float4 per row
            int v = li & 31;
            float4 val = *(const float4*)(W + (size_t)(k0 + row) * FDIM + v * 4);
            *(float4*)&Bs[row][v * 4] = val;
        }
        __syncthreads();

#pragma unroll
        for (int k = 0; k < BK; k++) {
            float a[TM];
            *(float4*)&a[0] = *(const float4*)&As[k][ty * TM];
            *(float4*)&a[4] = *(const float4*)&As[k][ty * TM + 4];
            // b pairs read directly as 64-bit lanes (LDS.128 x2)
            ulonglong2 b01 = *(const ulonglong2*)&Bs[k][tx * TN];
            ulonglong2 b23 = *(const ulonglong2*)&Bs[k][tx * TN + 4];
#pragma unroll
            for (int i = 0; i < TM; i++) {
                unsigned long long au = pack2(a[i], a[i]);
                FMA_F32X2(acc2[i][0], au, b01.x);
                FMA_F32X2(acc2[i][1], au, b01.y);
                FMA_F32X2(acc2[i][2], au, b23.x);
                FMA_F32X2(acc2[i][3], au, b23.y);
            }
        }
        __syncthreads();
    }

    // Epilogue
    float bv[TN], uv[TN];
#pragma unroll
    for (int j = 0; j < TN; j++) bv[j] = bias[tx * TN + j];
    if (EPI == 2) {
#pragma unroll
        for (int j = 0; j < TN; j++) uv[j] = U[tx * TN + j];
    }
#pragma unroll
    for (int i = 0; i < TM; i++) {
        int row = r0 + ty * TM + i;
        if (row < M) {
#pragma unroll
            for (int j2 = 0; j2 < TN / 2; j2++) {
                float v0, v1;
                unpack2(v0, v1, acc2[i][j2]);
#pragma unroll
                for (int h = 0; h < 2; h++) {
                    int j = j2 * 2 + h;
                    int col = tx * TN + j;
                    float z = (h ? v1 : v0) + bv[j];
                    float y;
                    if (EPI == 0)      y = sspf(z);
                    else if (EPI == 1) y = R[(size_t)row * FDIM + col] + z;
                    else               y = uv[j] * R[(size_t)row * FDIM + col] + z;
                    Y[(size_t)row * FDIM + col] = y;
                }
            }
        }
    }
}

// ---------------------------------------------------------------------------
// Fused message pass:
//   for each pair p: m[idx_i[p], :] += ( (cutoff[p]*rbf[p,:]) @ Wg ) * xj[idx_j[p], :]
// 128 threads = 128 features; Wg column in packed registers (32 x f32x2).
// idx_i sorted -> register accumulation with atomic flush on segment change.
// Inner product uses LDS.128 on desc (operands pre-packed in smem) + FFMA2.
// ---------------------------------------------------------------------------
#define MSG_T 128
#define MSG_PPB 512
#define MSG_S 16

__global__ __launch_bounds__(MSG_T)
void msg_k(const float* __restrict__ cutoffs, const float* __restrict__ rbfs,
           const int* __restrict__ idx_i, const int* __restrict__ idx_j,
           const float* __restrict__ Wg, const float* __restrict__ xj,
           float* __restrict__ m, int npairs)
{
    __shared__ __align__(16) float desc[MSG_S][KDIM];
    __shared__ int si[MSG_S], sj[MSG_S];

    const int t = threadIdx.x;
    // Wg column for this feature, packed as 32 f32x2 pairs
    unsigned long long wg2[KDIM / 2];
#pragma unroll
    for (int q = 0; q < KDIM / 2; q++)
        wg2[q] = pack2(Wg[(2 * q) * FDIM + t], Wg[(2 * q + 1) * FDIM + t]);

    const int p0 = blockIdx.x * MSG_PPB;
    const int pend = min(p0 + MSG_PPB, npairs);

    float acc = 0.0f;
    int prev = -1;

    for (int base = p0; base < pend; base += MSG_S) {
        int ns = min(MSG_S, pend - base);
        __syncthreads();
        // stage desc = cutoff * rbf, vectorized (16 float4 per pair-row)
        for (int li = t; li < ns * (KDIM / 4); li += MSG_T) {
            int s = li >> 4, v = li & 15;
            float c = cutoffs[base + s];
            float4 r = *(const float4*)&rbfs[(size_t)(base + s) * KDIM + v * 4];
            r.x *= c; r.y *= c; r.z *= c; r.w *= c;
            *(float4*)&desc[s][v * 4] = r;
        }
        if (t < ns) { si[t] = idx_i[base + t]; sj[t] = idx_j[base + t]; }
        __syncthreads();

        for (int s = 0; s < ns; s++) {
            int i = si[s], j = sj[s];
            if (i != prev) {
                if (prev >= 0) atomicAdd(&m[(size_t)prev * FDIM + t], acc);
                acc = 0.0f;
                prev = i;
            }
            float xv = xj[(size_t)j * FDIM + t];
            unsigned long long ga = 0ull, gb = 0ull;
#pragma unroll
            for (int q = 0; q < KDIM / 8; q++) {        // 8 x LDS.128 (broadcast)
                ulonglong2 d0 = *(const ulonglong2*)&desc[s][q * 8];
                ulonglong2 d1 = *(const ulonglong2*)&desc[s][q * 8 + 4];
                FMA_F32X2(ga, d0.x, wg2[q * 4 + 0]);
                FMA_F32X2(gb, d0.y, wg2[q * 4 + 1]);
                FMA_F32X2(ga, d1.x, wg2[q * 4 + 2]);
                FMA_F32X2(gb, d1.y, wg2[q * 4 + 3]);
            }
            float a0, a1, b0, b1;
            unpack2(a0, a1, ga);
            unpack2(b0, b1, gb);
            float g = (a0 + b0) + (a1 + b1);
            acc = fmaf(g, xv, acc);
        }
    }
    if (prev >= 0) atomicAdd(&m[(size_t)prev * FDIM + t], acc);
}

// ---------------------------------------------------------------------------
extern "C" void kernel_launch(void* const* d_in, const int* in_sizes, int n_in,
                              void* d_out, int out_size)
{
    const float* features = (const float*)d_in[0];
    const float* cutoffs  = (const float*)d_in[1];
    const float* rbfs     = (const float*)d_in[2];
    const int*   idx_i    = (const int*)d_in[3];
    const int*   idx_j    = (const int*)d_in[4];
    const float* Wg   = (const float*)d_in[5];
    const float* Wi   = (const float*)d_in[6];
    const float* bi   = (const float*)d_in[7];
    const float* Wj   = (const float*)d_in[8];
    const float* bj   = (const float*)d_in[9];
    const float* Wr1  = (const float*)d_in[10];
    const float* br1  = (const float*)d_in[11];
    const float* Wr2  = (const float*)d_in[12];
    const float* br2  = (const float*)d_in[13];
    const float* Wout = (const float*)d_in[14];
    const float* bout = (const float*)d_in[15];
    const float* u    = (const float*)d_in[16];
    const float* Wf1  = (const float*)d_in[17];
    const float* bf1  = (const float*)d_in[18];
    const float* Wf2  = (const float*)d_in[19];
    const float* bf2  = (const float*)d_in[20];
    const int npairs = in_sizes[1];
    float* out = (float*)d_out;

    float *xjp, *mp, *tp;
    cudaGetSymbolAddress((void**)&xjp, g_xj);
    cudaGetSymbolAddress((void**)&mp,  g_m);
    cudaGetSymbolAddress((void**)&tp,  g_t);

    const int gemmGrid = (NATOMS + BM - 1) / BM;
    const int msgGrid = (npairs + MSG_PPB - 1) / MSG_PPB;

    const float* x = features;
    for (int b = 0; b < NB; b++) {
        float* xout = out + (size_t)b * NATOMS * FDIM;

        // m  = xi = ssp(ssp(x) @ Wi + bi)   (ssp fused into A-load)
        gemm_k<1, 0><<<gemmGrid, 256>>>(x, Wi + (size_t)b * FDIM * FDIM,
                                        bi + b * FDIM, nullptr, nullptr, mp, NATOMS);
        // xj = ssp(ssp(x) @ Wj + bj)
        gemm_k<1, 0><<<gemmGrid, 256>>>(x, Wj + (size_t)b * FDIM * FDIM,
                                        bj + b * FDIM, nullptr, nullptr, xjp, NATOMS);
        // m += segment_sum( (desc @ Wg) * xj[idx_j], idx_i )
        msg_k<<<msgGrid, MSG_T>>>(cutoffs, rbfs, idx_i, idx_j,
                                  Wg + (size_t)b * KDIM * FDIM, xjp, mp, npairs);
        // interaction residuals
        for (int r = 0; r < NRI; r++) {
            const float* w1 = Wr1 + (size_t)(b * NRI + r) * FDIM * FDIM;
            const float* c1 = br1 + (size_t)(b * NRI + r) * FDIM;
            const float* w2 = Wr2 + (size_t)(b * NRI + r) * FDIM * FDIM;
            const float* c2 = br2 + (size_t)(b * NRI + r) * FDIM;
            gemm_k<1, 0><<<gemmGrid, 256>>>(mp, w1, c1, nullptr, nullptr, tp, NATOMS);
            gemm_k<0, 1><<<gemmGrid, 256>>>(tp, w2, c2, mp, nullptr, mp, NATOMS);
        }
        // x' = u*x + ssp(m) @ Wout + bout
        gemm_k<1, 2><<<gemmGrid, 256>>>(mp, Wout + (size_t)b * FDIM * FDIM,
                                        bout + b * FDIM, x, u + b * FDIM, xout, NATOMS);
        // feature residuals (in-place on output slab)
        for (int r = 0; r < NRF; r++) {
            const float* w1 = Wf1 + (size_t)(b * NRF + r) * FDIM * FDIM;
            const float* c1 = bf1 + (size_t)(b * NRF + r) * FDIM;
            const float* w2 = Wf2 + (size_t)(b * NRF + r) * FDIM * FDIM;
            const float* c2 = bf2 + (size_t)(b * NRF + r) * FDIM;
            gemm_k<1, 0><<<gemmGrid, 256>>>(xout, w1, c1, nullptr, nullptr, tp, NATOMS);
            gemm_k<0, 1><<<gemmGrid, 256>>>(tp, w2, c2, xout, nullptr, xout, NATOMS);
        }
        x = xout;
    }
}

// round 6
// speedup vs baseline: 1.6268x; 1.4421x over previous
#include <cuda_runtime.h>
#include <cuda_bf16.h>
#include <cstdint>

#define NATOMS 50000
#define FDIM 128
#define KDIM 64
#define NB 5
#define NRI 3
#define NRF 2
#define NWMAT 65   // 5 Wi + 5 Wj + 15 Wr1 + 15 Wr2 + 5 Wout + 10 Wf1 + 10 Wf2

// Scratch (allocation-free rule: __device__ globals)
__device__ float g_xj[NATOMS * FDIM];
__device__ float g_m [NATOMS * FDIM];
__device__ float g_t [NATOMS * FDIM];
// Per-lane prepacked B fragments: [slot][s(8)][t(16)][lane(32)] = uint4{bhi0,bhi1,blo0,blo1}
__device__ uint4 g_wfrag[(size_t)NWMAT * 4096];

__device__ __forceinline__ float sspf(float x) {
    return fmaxf(x, 0.0f) + log1pf(expf(-fabsf(x))) - 0.69314718055994530942f;
}

// ---- packed f32x2 helpers (msg_k) ----
__device__ __forceinline__ unsigned long long pack2(float lo, float hi) {
    unsigned long long r;
    asm("mov.b64 %0, {%1,%2};" : "=l"(r) : "f"(lo), "f"(hi));
    return r;
}
__device__ __forceinline__ void unpack2(float& lo, float& hi, unsigned long long v) {
    asm("mov.b64 {%0,%1}, %2;" : "=f"(lo), "=f"(hi) : "l"(v));
}
#define FMA_F32X2(d, a, b) \
    asm("fma.rn.f32x2 %0, %1, %2, %0;" : "+l"(d) : "l"(a), "l"(b))

// ---- bf16x2 pack: low 16 bits = bf16(lo), high = bf16(hi) ----
__device__ __forceinline__ uint32_t pack_bf(float lo, float hi) {
    uint32_t r;
    asm("cvt.rn.bf16x2.f32 %0, %1, %2;" : "=r"(r) : "f"(hi), "f"(lo));
    return r;
}
// split float2 -> bf16x2 hi fragment + bf16x2 lo (residual) fragment
__device__ __forceinline__ void split2(float a, float b, uint32_t& h, uint32_t& l) {
    h = pack_bf(a, b);
    float h0 = __uint_as_float(h << 16);
    float h1 = __uint_as_float(h & 0xFFFF0000u);
    l = pack_bf(a - h0, b - h1);
}

// m16n8k16 row.col f32.bf16.bf16.f32
#define MMA_BF16(d0, d1, d2, d3, a0, a1, a2, a3, b0, b1)                     \
    asm volatile("mma.sync.aligned.m16n8k16.row.col.f32.bf16.bf16.f32 "      \
                 "{%0,%1,%2,%3},{%4,%5,%6,%7},{%8,%9},{%0,%1,%2,%3};"        \
                 : "+f"(d0), "+f"(d1), "+f"(d2), "+f"(d3)                    \
                 : "r"(a0), "r"(a1), "r"(a2), "r"(a3), "r"(b0), "r"(b1))

// ---------------------------------------------------------------------------
// Weight prepass: pack each fp32 W [k=128][n=128] into per-lane bf16 B-fragments
// (hi and lo split). Fragment (s,t,lane): b0 covers k=16s+2c+{0,1}, b1 covers
// k=16s+2c+8+{0,1}, n = 8t + lane/4  (c = lane%4).
// grid = (32, 65), block = 128
// ---------------------------------------------------------------------------
__global__ void wfrag_k(const float* __restrict__ Wi, const float* __restrict__ Wj,
                        const float* __restrict__ Wr1, const float* __restrict__ Wr2,
                        const float* __restrict__ Wout, const float* __restrict__ Wf1,
                        const float* __restrict__ Wf2)
{
    int slot = blockIdx.y;
    const float* src;
    if (slot < 5)       src = Wi   + (size_t)slot * 16384;
    else if (slot < 10) src = Wj   + (size_t)(slot - 5) * 16384;
    else if (slot < 25) src = Wr1  + (size_t)(slot - 10) * 16384;
    else if (slot < 40) src = Wr2  + (size_t)(slot - 25) * 16384;
    else if (slot < 45) src = Wout + (size_t)(slot - 40) * 16384;
    else if (slot < 55) src = Wf1  + (size_t)(slot - 45) * 16384;
    else                src = Wf2  + (size_t)(slot - 55) * 16384;

    int q = blockIdx.x * 128 + threadIdx.x;   // 0..4095
    int l = q & 31, t = (q >> 5) & 15, s = q >> 9;
    int n = 8 * t + (l >> 2);
    int k0 = 16 * s + 2 * (l & 3);

    float w0 = src[(k0 + 0) * 128 + n];
    float w1 = src[(k0 + 1) * 128 + n];
    float w8 = src[(k0 + 8) * 128 + n];
    float w9 = src[(k0 + 9) * 128 + n];
    uint4 o;
    split2(w0, w1, o.x, o.z);
    split2(w8, w9, o.y, o.w);
    g_wfrag[(size_t)slot * 4096 + q] = o;
}

// ---------------------------------------------------------------------------
// Tensor-core GEMM: Y = epi( pre(X) @ W + bias ; R, U )
//   PRE=1 : ssp on X load     EPI=0: ssp(z)   EPI=1: R+z   EPI=2: U[col]*R+z
// CTA = 128 threads (4 warps), tile = 64 rows; warp tile m16 x n128.
// bf16 3-term split, fp32 accumulate. No shared memory.
// ---------------------------------------------------------------------------
template <int PRE, int EPI>
__global__ __launch_bounds__(128, 2)
void tmma_k(const float* __restrict__ X, const uint4* __restrict__ WF,
            const float* __restrict__ bias, const float* __restrict__ R,
            const float* __restrict__ U, float* __restrict__ Y, int M)
{
    const int tid = threadIdx.x;
    const int w = tid >> 5, l = tid & 31;
    const int c = l & 3, g = l >> 2;
    const int r0 = blockIdx.x * 64 + w * 16 + g;
    const int r1 = r0 + 8;
    const float* xr0 = X + (size_t)min(r0, M - 1) * FDIM;
    const float* xr1 = X + (size_t)min(r1, M - 1) * FDIM;

    // Build A fragments (hi/lo) for all 8 k-steps
    uint32_t ahi[8][4], alo[8][4];
#pragma unroll
    for (int s = 0; s < 8; s++) {
        int col0 = 16 * s + 2 * c;
        float2 v00 = *(const float2*)(xr0 + col0);
        float2 v10 = *(const float2*)(xr1 + col0);
        float2 v01 = *(const float2*)(xr0 + col0 + 8);
        float2 v11 = *(const float2*)(xr1 + col0 + 8);
        if (PRE) {
            v00.x = sspf(v00.x); v00.y = sspf(v00.y);
            v10.x = sspf(v10.x); v10.y = sspf(v10.y);
            v01.x = sspf(v01.x); v01.y = sspf(v01.y);
            v11.x = sspf(v11.x); v11.y = sspf(v11.y);
        }
        split2(v00.x, v00.y, ahi[s][0], alo[s][0]);
        split2(v10.x, v10.y, ahi[s][1], alo[s][1]);
        split2(v01.x, v01.y, ahi[s][2], alo[s][2]);
        split2(v11.x, v11.y, ahi[s][3], alo[s][3]);
    }

    const bool ok0 = (r0 < M), ok1 = (r1 < M);

#pragma unroll
    for (int t = 0; t < 16; t++) {
        float d0 = 0.f, d1 = 0.f, d2 = 0.f, d3 = 0.f;
#pragma unroll
        for (int s = 0; s < 8; s++) {
            uint4 b = WF[(size_t)((s * 16 + t) * 32 + l)];
            MMA_BF16(d0, d1, d2, d3, ahi[s][0], ahi[s][1], ahi[s][2], ahi[s][3], b.x, b.y);
            MMA_BF16(d0, d1, d2, d3, alo[s][0], alo[s][1], alo[s][2], alo[s][3], b.x, b.y);
            MMA_BF16(d0, d1, d2, d3, ahi[s][0], ahi[s][1], ahi[s][2], ahi[s][3], b.z, b.w);
        }
        const int col = 8 * t + 2 * c;
        float2 bv = *(const float2*)(bias + col);
        d0 += bv.x; d1 += bv.y; d2 += bv.x; d3 += bv.y;

        float2 o0, o1;
        if (EPI == 0) {
            o0.x = sspf(d0); o0.y = sspf(d1);
            o1.x = sspf(d2); o1.y = sspf(d3);
        } else if (EPI == 1) {
            float2 rv0 = ok0 ? *(const float2*)(R + (size_t)r0 * FDIM + col) : make_float2(0.f, 0.f);
            float2 rv1 = ok1 ? *(const float2*)(R + (size_t)r1 * FDIM + col) : make_float2(0.f, 0.f);
            o0.x = rv0.x + d0; o0.y = rv0.y + d1;
            o1.x = rv1.x + d2; o1.y = rv1.y + d3;
        } else {
            float2 uv = *(const float2*)(U + col);
            float2 rv0 = ok0 ? *(const float2*)(R + (size_t)r0 * FDIM + col) : make_float2(0.f, 0.f);
            float2 rv1 = ok1 ? *(const float2*)(R + (size_t)r1 * FDIM + col) : make_float2(0.f, 0.f);
            o0.x = fmaf(uv.x, rv0.x, d0); o0.y = fmaf(uv.y, rv0.y, d1);
            o1.x = fmaf(uv.x, rv1.x, d2); o1.y = fmaf(uv.y, rv1.y, d3);
        }
        if (ok0) *(float2*)(Y + (size_t)r0 * FDIM + col) = o0;
        if (ok1) *(float2*)(Y + (size_t)r1 * FDIM + col) = o1;
    }
}

// ---------------------------------------------------------------------------
// Fused message pass (unchanged)
// ---------------------------------------------------------------------------
#define MSG_T 128
#define MSG_PPB 512
#define MSG_S 16

__global__ __launch_bounds__(MSG_T)
void msg_k(const float* __restrict__ cutoffs, const float* __restrict__ rbfs,
           const int* __restrict__ idx_i, const int* __restrict__ idx_j,
           const float* __restrict__ Wg, const float* __restrict__ xj,
           float* __restrict__ m, int npairs)
{
    __shared__ __align__(16) float desc[MSG_S][KDIM];
    __shared__ int si[MSG_S], sj[MSG_S];

    const int t = threadIdx.x;
    unsigned long long wg2[KDIM / 2];
#pragma unroll
    for (int q = 0; q < KDIM / 2; q++)
        wg2[q] = pack2(Wg[(2 * q) * FDIM + t], Wg[(2 * q + 1) * FDIM + t]);

    const int p0 = blockIdx.x * MSG_PPB;
    const int pend = min(p0 + MSG_PPB, npairs);

    float acc = 0.0f;
    int prev = -1;

    for (int base = p0; base < pend; base += MSG_S) {
        int ns = min(MSG_S, pend - base);
        __syncthreads();
        for (int li = t; li < ns * (KDIM / 4); li += MSG_T) {
            int s = li >> 4, v = li & 15;
            float c = cutoffs[base + s];
            float4 r = *(const float4*)&rbfs[(size_t)(base + s) * KDIM + v * 4];
            r.x *= c; r.y *= c; r.z *= c; r.w *= c;
            *(float4*)&desc[s][v * 4] = r;
        }
        if (t < ns) { si[t] = idx_i[base + t]; sj[t] = idx_j[base + t]; }
        __syncthreads();

        for (int s = 0; s < ns; s++) {
            int i = si[s], j = sj[s];
            if (i != prev) {
                if (prev >= 0) atomicAdd(&m[(size_t)prev * FDIM + t], acc);
                acc = 0.0f;
                prev = i;
            }
            float xv = xj[(size_t)j * FDIM + t];
            unsigned long long ga = 0ull, gb = 0ull;
#pragma unroll
            for (int q = 0; q < KDIM / 8; q++) {
                ulonglong2 d0 = *(const ulonglong2*)&desc[s][q * 8];
                ulonglong2 d1 = *(const ulonglong2*)&desc[s][q * 8 + 4];
                FMA_F32X2(ga, d0.x, wg2[q * 4 + 0]);
                FMA_F32X2(gb, d0.y, wg2[q * 4 + 1]);
                FMA_F32X2(ga, d1.x, wg2[q * 4 + 2]);
                FMA_F32X2(gb, d1.y, wg2[q * 4 + 3]);
            }
            float a0, a1, b0, b1;
            unpack2(a0, a1, ga);
            unpack2(b0, b1, gb);
            float g = (a0 + b0) + (a1 + b1);
            acc = fmaf(g, xv, acc);
        }
    }
    if (prev >= 0) atomicAdd(&m[(size_t)prev * FDIM + t], acc);
}

// ---------------------------------------------------------------------------
extern "C" void kernel_launch(void* const* d_in, const int* in_sizes, int n_in,
                              void* d_out, int out_size)
{
    const float* features = (const float*)d_in[0];
    const float* cutoffs  = (const float*)d_in[1];
    const float* rbfs     = (const float*)d_in[2];
    const int*   idx_i    = (const int*)d_in[3];
    const int*   idx_j    = (const int*)d_in[4];
    const float* Wg   = (const float*)d_in[5];
    const float* Wi   = (const float*)d_in[6];
    const float* bi   = (const float*)d_in[7];
    const float* Wj   = (const float*)d_in[8];
    const float* bj   = (const float*)d_in[9];
    const float* Wr1  = (const float*)d_in[10];
    const float* br1  = (const float*)d_in[11];
    const float* Wr2  = (const float*)d_in[12];
    const float* br2  = (const float*)d_in[13];
    const float* Wout = (const float*)d_in[14];
    const float* bout = (const float*)d_in[15];
    const float* u    = (const float*)d_in[16];
    const float* Wf1  = (const float*)d_in[17];
    const float* bf1  = (const float*)d_in[18];
    const float* Wf2  = (const float*)d_in[19];
    const float* bf2  = (const float*)d_in[20];
    const int npairs = in_sizes[1];
    float* out = (float*)d_out;

    float *xjp, *mp, *tp;
    uint4* wfrag;
    cudaGetSymbolAddress((void**)&xjp, g_xj);
    cudaGetSymbolAddress((void**)&mp,  g_m);
    cudaGetSymbolAddress((void**)&tp,  g_t);
    cudaGetSymbolAddress((void**)&wfrag, g_wfrag);

    const int gemmGrid = (NATOMS + 63) / 64;
    const int msgGrid = (npairs + MSG_PPB - 1) / MSG_PPB;

    // weight fragment prepass (cheap; runs once per launch)
    wfrag_k<<<dim3(32, NWMAT), 128>>>(Wi, Wj, Wr1, Wr2, Wout, Wf1, Wf2);

    auto WFr = [&](int slot) { return wfrag + (size_t)slot * 4096; };

    const float* x = features;
    for (int b = 0; b < NB; b++) {
        float* xout = out + (size_t)b * NATOMS * FDIM;

        // m = xi = ssp(ssp(x) @ Wi + bi)
        tmma_k<1, 0><<<gemmGrid, 128>>>(x, WFr(b), bi + b * FDIM,
                                        nullptr, nullptr, mp, NATOMS);
        // xj = ssp(ssp(x) @ Wj + bj)
        tmma_k<1, 0><<<gemmGrid, 128>>>(x, WFr(5 + b), bj + b * FDIM,
                                        nullptr, nullptr, xjp, NATOMS);
        // m += segment_sum( (desc @ Wg) * xj[idx_j], idx_i )
        msg_k<<<msgGrid, MSG_T>>>(cutoffs, rbfs, idx_i, idx_j,
                                  Wg + (size_t)b * KDIM * FDIM, xjp, mp, npairs);
        // interaction residuals
        for (int r = 0; r < NRI; r++) {
            int s1 = 10 + b * NRI + r, s2 = 25 + b * NRI + r;
            tmma_k<1, 0><<<gemmGrid, 128>>>(mp, WFr(s1),
                    br1 + (size_t)(b * NRI + r) * FDIM, nullptr, nullptr, tp, NATOMS);
            tmma_k<0, 1><<<gemmGrid, 128>>>(tp, WFr(s2),
                    br2 + (size_t)(b * NRI + r) * FDIM, mp, nullptr, mp, NATOMS);
        }
        // x' = u*x + ssp(m) @ Wout + bout
        tmma_k<1, 2><<<gemmGrid, 128>>>(mp, WFr(40 + b), bout + b * FDIM,
                                        x, u + b * FDIM, xout, NATOMS);
        // feature residuals
        for (int r = 0; r < NRF; r++) {
            int s1 = 45 + b * NRF + r, s2 = 55 + b * NRF + r;
            tmma_k<1, 0><<<gemmGrid, 128>>>(xout, WFr(s1),
                    bf1 + (size_t)(b * NRF + r) * FDIM, nullptr, nullptr, tp, NATOMS);
            tmma_k<0, 1><<<gemmGrid, 128>>>(tp, WFr(s2),
                    bf2 + (size_t)(b * NRF + r) * FDIM, xout, nullptr, xout, NATOMS);
        }
        x = xout;
    }
}

// round 7
// speedup vs baseline: 1.9056x; 1.1714x over previous
#include <cuda_runtime.h>
#include <cuda_bf16.h>
#include <cstdint>

#define NATOMS 50000
#define FDIM 128
#define KDIM 64
#define NB 5
#define NRI 3
#define NRF 2
#define NWMAT 65   // 5 Wi + 5 Wj + 15 Wr1 + 15 Wr2 + 5 Wout + 10 Wf1 + 10 Wf2

// Scratch (allocation-free rule: __device__ globals)
__device__ float g_xj[NATOMS * FDIM];
__device__ float g_m [NATOMS * FDIM];
__device__ float g_t [NATOMS * FDIM];
// Per-lane prepacked B fragments: [slot][s(8)][t(16)][lane(32)] = uint4{bhi0,bhi1,blo0,blo1}
__device__ uint4 g_wfrag[(size_t)NWMAT * 4096];
// Wg fragments: [slot(5)][s(4)][t(16)][lane(32)]
__device__ uint4 g_gfrag[(size_t)NB * 2048];

__device__ __forceinline__ float sspf(float x) {
    return fmaxf(x, 0.0f) + log1pf(expf(-fabsf(x))) - 0.69314718055994530942f;
}

// ---- bf16x2 pack: low 16 bits = bf16(lo), high = bf16(hi) ----
__device__ __forceinline__ uint32_t pack_bf(float lo, float hi) {
    uint32_t r;
    asm("cvt.rn.bf16x2.f32 %0, %1, %2;" : "=r"(r) : "f"(hi), "f"(lo));
    return r;
}
// split float2 -> bf16x2 hi fragment + bf16x2 lo (residual) fragment
__device__ __forceinline__ void split2(float a, float b, uint32_t& h, uint32_t& l) {
    h = pack_bf(a, b);
    float h0 = __uint_as_float(h << 16);
    float h1 = __uint_as_float(h & 0xFFFF0000u);
    l = pack_bf(a - h0, b - h1);
}

// m16n8k16 row.col f32.bf16.bf16.f32
#define MMA_BF16(d0, d1, d2, d3, a0, a1, a2, a3, b0, b1)                     \
    asm volatile("mma.sync.aligned.m16n8k16.row.col.f32.bf16.bf16.f32 "      \
                 "{%0,%1,%2,%3},{%4,%5,%6,%7},{%8,%9},{%0,%1,%2,%3};"        \
                 : "+f"(d0), "+f"(d1), "+f"(d2), "+f"(d3)                    \
                 : "r"(a0), "r"(a1), "r"(a2), "r"(a3), "r"(b0), "r"(b1))

// ---------------------------------------------------------------------------
// Weight prepass: pack each fp32 W [k=128][n=128] into per-lane bf16 B-fragments
// grid = (32, 65), block = 128
// ---------------------------------------------------------------------------
__global__ void wfrag_k(const float* __restrict__ Wi, const float* __restrict__ Wj,
                        const float* __restrict__ Wr1, const float* __restrict__ Wr2,
                        const float* __restrict__ Wout, const float* __restrict__ Wf1,
                        const float* __restrict__ Wf2)
{
    int slot = blockIdx.y;
    const float* src;
    if (slot < 5)       src = Wi   + (size_t)slot * 16384;
    else if (slot < 10) src = Wj   + (size_t)(slot - 5) * 16384;
    else if (slot < 25) src = Wr1  + (size_t)(slot - 10) * 16384;
    else if (slot < 40) src = Wr2  + (size_t)(slot - 25) * 16384;
    else if (slot < 45) src = Wout + (size_t)(slot - 40) * 16384;
    else if (slot < 55) src = Wf1  + (size_t)(slot - 45) * 16384;
    else                src = Wf2  + (size_t)(slot - 55) * 16384;

    int q = blockIdx.x * 128 + threadIdx.x;   // 0..4095
    int l = q & 31, t = (q >> 5) & 15, s = q >> 9;
    int n = 8 * t + (l >> 2);
    int k0 = 16 * s + 2 * (l & 3);

    float w0 = src[(k0 + 0) * 128 + n];
    float w1 = src[(k0 + 1) * 128 + n];
    float w8 = src[(k0 + 8) * 128 + n];
    float w9 = src[(k0 + 9) * 128 + n];
    uint4 o;
    split2(w0, w1, o.x, o.z);
    split2(w8, w9, o.y, o.w);
    g_wfrag[(size_t)slot * 4096 + q] = o;
}

// Wg prepass: [5][K=64][F=128] -> per-lane fragments. grid (16, 5), block 128
__global__ void wgfrag_k(const float* __restrict__ Wg)
{
    int slot = blockIdx.y;
    const float* src = Wg + (size_t)slot * KDIM * FDIM;
    int q = blockIdx.x * 128 + threadIdx.x;   // 0..2047
    int l = q & 31, t = (q >> 5) & 15, s = q >> 9;   // s 0..3
    int n = 8 * t + (l >> 2);
    int k0 = 16 * s + 2 * (l & 3);
    float w0 = src[(k0 + 0) * 128 + n];
    float w1 = src[(k0 + 1) * 128 + n];
    float w8 = src[(k0 + 8) * 128 + n];
    float w9 = src[(k0 + 9) * 128 + n];
    uint4 o;
    split2(w0, w1, o.x, o.z);
    split2(w8, w9, o.y, o.w);
    g_gfrag[(size_t)slot * 2048 + q] = o;
}

// ---------------------------------------------------------------------------
// Tensor-core GEMM: Y = epi( pre(X) @ W + bias ; R, U )
//   PRE=1 : ssp on X load     EPI=0: ssp(z)   EPI=1: R+z   EPI=2: U[col]*R+z
// CTA = 128 threads (4 warps), tile = 64 rows; warp tile m16 x n128.
// ---------------------------------------------------------------------------
template <int PRE, int EPI>
__global__ __launch_bounds__(128, 2)
void tmma_k(const float* __restrict__ X, const uint4* __restrict__ WF,
            const float* __restrict__ bias, const float* __restrict__ R,
            const float* __restrict__ U, float* __restrict__ Y, int M)
{
    const int tid = threadIdx.x;
    const int w = tid >> 5, l = tid & 31;
    const int c = l & 3, g = l >> 2;
    const int r0 = blockIdx.x * 64 + w * 16 + g;
    const int r1 = r0 + 8;
    const float* xr0 = X + (size_t)min(r0, M - 1) * FDIM;
    const float* xr1 = X + (size_t)min(r1, M - 1) * FDIM;

    uint32_t ahi[8][4], alo[8][4];
#pragma unroll
    for (int s = 0; s < 8; s++) {
        int col0 = 16 * s + 2 * c;
        float2 v00 = *(const float2*)(xr0 + col0);
        float2 v10 = *(const float2*)(xr1 + col0);
        float2 v01 = *(const float2*)(xr0 + col0 + 8);
        float2 v11 = *(const float2*)(xr1 + col0 + 8);
        if (PRE) {
            v00.x = sspf(v00.x); v00.y = sspf(v00.y);
            v10.x = sspf(v10.x); v10.y = sspf(v10.y);
            v01.x = sspf(v01.x); v01.y = sspf(v01.y);
            v11.x = sspf(v11.x); v11.y = sspf(v11.y);
        }
        split2(v00.x, v00.y, ahi[s][0], alo[s][0]);
        split2(v10.x, v10.y, ahi[s][1], alo[s][1]);
        split2(v01.x, v01.y, ahi[s][2], alo[s][2]);
        split2(v11.x, v11.y, ahi[s][3], alo[s][3]);
    }

    const bool ok0 = (r0 < M), ok1 = (r1 < M);

#pragma unroll
    for (int t = 0; t < 16; t++) {
        float d0 = 0.f, d1 = 0.f, d2 = 0.f, d3 = 0.f;
#pragma unroll
        for (int s = 0; s < 8; s++) {
            uint4 b = WF[(size_t)((s * 16 + t) * 32 + l)];
            MMA_BF16(d0, d1, d2, d3, ahi[s][0], ahi[s][1], ahi[s][2], ahi[s][3], b.x, b.y);
            MMA_BF16(d0, d1, d2, d3, alo[s][0], alo[s][1], alo[s][2], alo[s][3], b.x, b.y);
            MMA_BF16(d0, d1, d2, d3, ahi[s][0], ahi[s][1], ahi[s][2], ahi[s][3], b.z, b.w);
        }
        const int col = 8 * t + 2 * c;
        float2 bv = *(const float2*)(bias + col);
        d0 += bv.x; d1 += bv.y; d2 += bv.x; d3 += bv.y;

        float2 o0, o1;
        if (EPI == 0) {
            o0.x = sspf(d0); o0.y = sspf(d1);
            o1.x = sspf(d2); o1.y = sspf(d3);
        } else if (EPI == 1) {
            float2 rv0 = ok0 ? *(const float2*)(R + (size_t)r0 * FDIM + col) : make_float2(0.f, 0.f);
            float2 rv1 = ok1 ? *(const float2*)(R + (size_t)r1 * FDIM + col) : make_float2(0.f, 0.f);
            o0.x = rv0.x + d0; o0.y = rv0.y + d1;
            o1.x = rv1.x + d2; o1.y = rv1.y + d3;
        } else {
            float2 uv = *(const float2*)(U + col);
            float2 rv0 = ok0 ? *(const float2*)(R + (size_t)r0 * FDIM + col) : make_float2(0.f, 0.f);
            float2 rv1 = ok1 ? *(const float2*)(R + (size_t)r1 * FDIM + col) : make_float2(0.f, 0.f);
            o0.x = fmaf(uv.x, rv0.x, d0); o0.y = fmaf(uv.y, rv0.y, d1);
            o1.x = fmaf(uv.x, rv1.x, d2); o1.y = fmaf(uv.y, rv1.y, d3);
        }
        if (ok0) *(float2*)(Y + (size_t)r0 * FDIM + col) = o0;
        if (ok1) *(float2*)(Y + (size_t)r1 * FDIM + col) = o1;
    }
}

// ---------------------------------------------------------------------------
// Fused xi/xj GEMM: shared ssp+split A-fragments, two weight sets / outputs.
// Y1 = ssp(ssp(X)@W1 + b1), Y2 = ssp(ssp(X)@W2 + b2)
// ---------------------------------------------------------------------------
__global__ __launch_bounds__(128, 2)
void tmma2_k(const float* __restrict__ X,
             const uint4* __restrict__ WF1, const float* __restrict__ b1, float* __restrict__ Y1,
             const uint4* __restrict__ WF2, const float* __restrict__ b2, float* __restrict__ Y2,
             int M)
{
    const int tid = threadIdx.x;
    const int w = tid >> 5, l = tid & 31;
    const int c = l & 3, g = l >> 2;
    const int r0 = blockIdx.x * 64 + w * 16 + g;
    const int r1 = r0 + 8;
    const float* xr0 = X + (size_t)min(r0, M - 1) * FDIM;
    const float* xr1 = X + (size_t)min(r1, M - 1) * FDIM;

    uint32_t ahi[8][4], alo[8][4];
#pragma unroll
    for (int s = 0; s < 8; s++) {
        int col0 = 16 * s + 2 * c;
        float2 v00 = *(const float2*)(xr0 + col0);
        float2 v10 = *(const float2*)(xr1 + col0);
        float2 v01 = *(const float2*)(xr0 + col0 + 8);
        float2 v11 = *(const float2*)(xr1 + col0 + 8);
        v00.x = sspf(v00.x); v00.y = sspf(v00.y);
        v10.x = sspf(v10.x); v10.y = sspf(v10.y);
        v01.x = sspf(v01.x); v01.y = sspf(v01.y);
        v11.x = sspf(v11.x); v11.y = sspf(v11.y);
        split2(v00.x, v00.y, ahi[s][0], alo[s][0]);
        split2(v10.x, v10.y, ahi[s][1], alo[s][1]);
        split2(v01.x, v01.y, ahi[s][2], alo[s][2]);
        split2(v11.x, v11.y, ahi[s][3], alo[s][3]);
    }

    const bool ok0 = (r0 < M), ok1 = (r1 < M);

#pragma unroll
    for (int m = 0; m < 2; m++) {
        const uint4* WF = m ? WF2 : WF1;
        const float* bias = m ? b2 : b1;
        float* Y = m ? Y2 : Y1;
#pragma unroll
        for (int t = 0; t < 16; t++) {
            float d0 = 0.f, d1 = 0.f, d2 = 0.f, d3 = 0.f;
#pragma unroll
            for (int s = 0; s < 8; s++) {
                uint4 b = WF[(size_t)((s * 16 + t) * 32 + l)];
                MMA_BF16(d0, d1, d2, d3, ahi[s][0], ahi[s][1], ahi[s][2], ahi[s][3], b.x, b.y);
                MMA_BF16(d0, d1, d2, d3, alo[s][0], alo[s][1], alo[s][2], alo[s][3], b.x, b.y);
                MMA_BF16(d0, d1, d2, d3, ahi[s][0], ahi[s][1], ahi[s][2], ahi[s][3], b.z, b.w);
            }
            const int col = 8 * t + 2 * c;
            float2 bv = *(const float2*)(bias + col);
            float2 o0, o1;
            o0.x = sspf(d0 + bv.x); o0.y = sspf(d1 + bv.y);
            o1.x = sspf(d2 + bv.x); o1.y = sspf(d3 + bv.y);
            if (ok0) *(float2*)(Y + (size_t)r0 * FDIM + col) = o0;
            if (ok1) *(float2*)(Y + (size_t)r1 * FDIM + col) = o1;
        }
    }
}

// ---------------------------------------------------------------------------
// Fused message pass, tensor-core filter:
// per 16-pair chunk: (a) stage desc, (b) g = desc @ Wg via MMA -> smem,
// (c) per-feature segment accumulate m[i] += g * xj[j].
// ---------------------------------------------------------------------------
#define MSG_T 128
#define MSG_PPB 512
#define DESC_P 68   // padded row (floats) for conflict-free frag loads
#define GSM_P 132

__global__ __launch_bounds__(MSG_T)
void msgmma_k(const float* __restrict__ cutoffs, const float* __restrict__ rbfs,
              const int* __restrict__ idx_i, const int* __restrict__ idx_j,
              const uint4* __restrict__ GF, const float* __restrict__ xj,
              float* __restrict__ m, int npairs)
{
    __shared__ __align__(16) float desc[16][DESC_P];
    __shared__ __align__(16) float gsm[16][GSM_P];
    __shared__ int si[16], sj[16];

    const int t = threadIdx.x;
    const int w = t >> 5, l = t & 31;
    const int c = l & 3, g = l >> 2;

    const int p0 = blockIdx.x * MSG_PPB;
    const int pend = min(p0 + MSG_PPB, npairs);

    float acc = 0.0f;
    int prev = -1;

    for (int base = p0; base < pend; base += 16) {
        const int ns = min(16, pend - base);
        __syncthreads();   // prev chunk phase-c done with gsm/si/sj
        // ---- stage desc = cutoff * rbf ----
        for (int li = t; li < ns * 16; li += MSG_T) {
            int s = li >> 4, v = li & 15;
            float cf = cutoffs[base + s];
            float4 r = *(const float4*)&rbfs[(size_t)(base + s) * KDIM + v * 4];
            r.x *= cf; r.y *= cf; r.z *= cf; r.w *= cf;
            *(float4*)&desc[s][v * 4] = r;
        }
        if (t < ns) { si[t] = idx_i[base + t]; sj[t] = idx_j[base + t]; }
        __syncthreads();

        // ---- phase a: g tile via MMA; warp w covers n-tiles 4w..4w+3 ----
        uint32_t ahi[4][4], alo[4][4];
#pragma unroll
        for (int s = 0; s < 4; s++) {
            int k0 = 16 * s + 2 * c;
            float2 v00 = *(const float2*)&desc[g][k0];
            float2 v10 = *(const float2*)&desc[g + 8][k0];
            float2 v01 = *(const float2*)&desc[g][k0 + 8];
            float2 v11 = *(const float2*)&desc[g + 8][k0 + 8];
            split2(v00.x, v00.y, ahi[s][0], alo[s][0]);
            split2(v10.x, v10.y, ahi[s][1], alo[s][1]);
            split2(v01.x, v01.y, ahi[s][2], alo[s][2]);
            split2(v11.x, v11.y, ahi[s][3], alo[s][3]);
        }
#pragma unroll
        for (int j = 0; j < 4; j++) {
            const int tt = 4 * w + j;
            float d0 = 0.f, d1 = 0.f, d2 = 0.f, d3 = 0.f;
#pragma unroll
            for (int s = 0; s < 4; s++) {
                uint4 b = GF[(size_t)((s * 16 + tt) * 32 + l)];
                MMA_BF16(d0, d1, d2, d3, ahi[s][0], ahi[s][1], ahi[s][2], ahi[s][3], b.x, b.y);
                MMA_BF16(d0, d1, d2, d3, alo[s][0], alo[s][1], alo[s][2], alo[s][3], b.x, b.y);
                MMA_BF16(d0, d1, d2, d3, ahi[s][0], ahi[s][1], ahi[s][2], ahi[s][3], b.z, b.w);
            }
            const int col = 8 * tt + 2 * c;
            *(float2*)&gsm[g][col] = make_float2(d0, d1);
            *(float2*)&gsm[g + 8][col] = make_float2(d2, d3);
        }
        __syncthreads();

        // ---- phase c: per-feature segment accumulate ----
#pragma unroll
        for (int s = 0; s < 16; s++) {
            if (s >= ns) break;
            int i = si[s], j = sj[s];
            if (i != prev) {
                if (prev >= 0) atomicAdd(&m[(size_t)prev * FDIM + t], acc);
                acc = 0.0f;
                prev = i;
            }
            acc = fmaf(gsm[s][t], xj[(size_t)j * FDIM + t], acc);
        }
    }
    if (prev >= 0) atomicAdd(&m[(size_t)prev * FDIM + t], acc);
}

// ---------------------------------------------------------------------------
extern "C" void kernel_launch(void* const* d_in, const int* in_sizes, int n_in,
                              void* d_out, int out_size)
{
    const float* features = (const float*)d_in[0];
    const float* cutoffs  = (const float*)d_in[1];
    const float* rbfs     = (const float*)d_in[2];
    const int*   idx_i    = (const int*)d_in[3];
    const int*   idx_j    = (const int*)d_in[4];
    const float* Wg   = (const float*)d_in[5];
    const float* Wi   = (const float*)d_in[6];
    const float* bi   = (const float*)d_in[7];
    const float* Wj   = (const float*)d_in[8];
    const float* bj   = (const float*)d_in[9];
    const float* Wr1  = (const float*)d_in[10];
    const float* br1  = (const float*)d_in[11];
    const float* Wr2  = (const float*)d_in[12];
    const float* br2  = (const float*)d_in[13];
    const float* Wout = (const float*)d_in[14];
    const float* bout = (const float*)d_in[15];
    const float* u    = (const float*)d_in[16];
    const float* Wf1  = (const float*)d_in[17];
    const float* bf1  = (const float*)d_in[18];
    const float* Wf2  = (const float*)d_in[19];
    const float* bf2  = (const float*)d_in[20];
    const int npairs = in_sizes[1];
    float* out = (float*)d_out;

    float *xjp, *mp, *tp;
    uint4 *wfrag, *gfrag;
    cudaGetSymbolAddress((void**)&xjp, g_xj);
    cudaGetSymbolAddress((void**)&mp,  g_m);
    cudaGetSymbolAddress((void**)&tp,  g_t);
    cudaGetSymbolAddress((void**)&wfrag, g_wfrag);
    cudaGetSymbolAddress((void**)&gfrag, g_gfrag);

    const int gemmGrid = (NATOMS + 63) / 64;
    const int msgGrid = (npairs + MSG_PPB - 1) / MSG_PPB;

    // prepasses (cheap; once per launch)
    wfrag_k<<<dim3(32, NWMAT), 128>>>(Wi, Wj, Wr1, Wr2, Wout, Wf1, Wf2);
    wgfrag_k<<<dim3(16, NB), 128>>>(Wg);

    auto WFr = [&](int slot) { return wfrag + (size_t)slot * 4096; };

    const float* x = features;
    for (int b = 0; b < NB; b++) {
        float* xout = out + (size_t)b * NATOMS * FDIM;

        // m = xi = ssp(ssp(x)@Wi+bi);  xj = ssp(ssp(x)@Wj+bj)   (fused)
        tmma2_k<<<gemmGrid, 128>>>(x, WFr(b), bi + b * FDIM, mp,
                                   WFr(5 + b), bj + b * FDIM, xjp, NATOMS);
        // m += segment_sum( (desc @ Wg) * xj[idx_j], idx_i )
        msgmma_k<<<msgGrid, MSG_T>>>(cutoffs, rbfs, idx_i, idx_j,
                                     gfrag + (size_t)b * 2048, xjp, mp, npairs);
        // interaction residuals
        for (int r = 0; r < NRI; r++) {
            int s1 = 10 + b * NRI + r, s2 = 25 + b * NRI + r;
            tmma_k<1, 0><<<gemmGrid, 128>>>(mp, WFr(s1),
                    br1 + (size_t)(b * NRI + r) * FDIM, nullptr, nullptr, tp, NATOMS);
            tmma_k<0, 1><<<gemmGrid, 128>>>(tp, WFr(s2),
                    br2 + (size_t)(b * NRI + r) * FDIM, mp, nullptr, mp, NATOMS);
        }
        // x' = u*x + ssp(m) @ Wout + bout
        tmma_k<1, 2><<<gemmGrid, 128>>>(mp, WFr(40 + b), bout + b * FDIM,
                                        x, u + b * FDIM, xout, NATOMS);
        // feature residuals
        for (int r = 0; r < NRF; r++) {
            int s1 = 45 + b * NRF + r, s2 = 55 + b * NRF + r;
            tmma_k<1, 0><<<gemmGrid, 128>>>(xout, WFr(s1),
                    bf1 + (size_t)(b * NRF + r) * FDIM, nullptr, nullptr, tp, NATOMS);
            tmma_k<0, 1><<<gemmGrid, 128>>>(tp, WFr(s2),
                    bf2 + (size_t)(b * NRF + r) * FDIM, xout, nullptr, xout, NATOMS);
        }
        x = xout;
    }
}

// round 8
// speedup vs baseline: 2.0771x; 1.0900x over previous
#include <cuda_runtime.h>
#include <cuda_bf16.h>
#include <cstdint>

#define NATOMS 50000
#define FDIM 128
#define KDIM 64
#define NB 5
#define NRI 3
#define NRF 2
#define NWMAT 65   // 5 Wi + 5 Wj + 15 Wr1 + 15 Wr2 + 5 Wout + 10 Wf1 + 10 Wf2

// Scratch (allocation-free rule: __device__ globals)
__device__ float g_xj[NATOMS * FDIM];
__device__ float g_m [NATOMS * FDIM];
// Per-lane prepacked B fragments: [slot][s(8)][t(16)][lane(32)] = uint4{bhi0,bhi1,blo0,blo1}
__device__ uint4 g_wfrag[(size_t)NWMAT * 4096];
// Wg fragments: [slot(5)][s(4)][t(16)][lane(32)]
__device__ uint4 g_gfrag[(size_t)NB * 2048];

__device__ __forceinline__ float sspf(float x) {
    return fmaxf(x, 0.0f) + log1pf(expf(-fabsf(x))) - 0.69314718055994530942f;
}

// ---- bf16x2 pack: low 16 bits = bf16(lo), high = bf16(hi) ----
__device__ __forceinline__ uint32_t pack_bf(float lo, float hi) {
    uint32_t r;
    asm("cvt.rn.bf16x2.f32 %0, %1, %2;" : "=r"(r) : "f"(hi), "f"(lo));
    return r;
}
// split float2 -> bf16x2 hi fragment + bf16x2 lo (residual) fragment
__device__ __forceinline__ void split2(float a, float b, uint32_t& h, uint32_t& l) {
    h = pack_bf(a, b);
    float h0 = __uint_as_float(h << 16);
    float h1 = __uint_as_float(h & 0xFFFF0000u);
    l = pack_bf(a - h0, b - h1);
}

// m16n8k16 row.col f32.bf16.bf16.f32
#define MMA_BF16(d0, d1, d2, d3, a0, a1, a2, a3, b0, b1)                     \
    asm volatile("mma.sync.aligned.m16n8k16.row.col.f32.bf16.bf16.f32 "      \
                 "{%0,%1,%2,%3},{%4,%5,%6,%7},{%8,%9},{%0,%1,%2,%3};"        \
                 : "+f"(d0), "+f"(d1), "+f"(d2), "+f"(d3)                    \
                 : "r"(a0), "r"(a1), "r"(a2), "r"(a3), "r"(b0), "r"(b1))

// 3-term split MMA macro
#define MMA3(d0, d1, d2, d3, AH, AL, b)                                          \
    do {                                                                         \
        MMA_BF16(d0, d1, d2, d3, AH[0], AH[1], AH[2], AH[3], (b).x, (b).y);      \
        MMA_BF16(d0, d1, d2, d3, AL[0], AL[1], AL[2], AL[3], (b).x, (b).y);      \
        MMA_BF16(d0, d1, d2, d3, AH[0], AH[1], AH[2], AH[3], (b).z, (b).w);      \
    } while (0)

// ---------------------------------------------------------------------------
// Weight prepass
// ---------------------------------------------------------------------------
__global__ void wfrag_k(const float* __restrict__ Wi, const float* __restrict__ Wj,
                        const float* __restrict__ Wr1, const float* __restrict__ Wr2,
                        const float* __restrict__ Wout, const float* __restrict__ Wf1,
                        const float* __restrict__ Wf2)
{
    int slot = blockIdx.y;
    const float* src;
    if (slot < 5)       src = Wi   + (size_t)slot * 16384;
    else if (slot < 10) src = Wj   + (size_t)(slot - 5) * 16384;
    else if (slot < 25) src = Wr1  + (size_t)(slot - 10) * 16384;
    else if (slot < 40) src = Wr2  + (size_t)(slot - 25) * 16384;
    else if (slot < 45) src = Wout + (size_t)(slot - 40) * 16384;
    else if (slot < 55) src = Wf1  + (size_t)(slot - 45) * 16384;
    else                src = Wf2  + (size_t)(slot - 55) * 16384;

    int q = blockIdx.x * 128 + threadIdx.x;   // 0..4095
    int l = q & 31, t = (q >> 5) & 15, s = q >> 9;
    int n = 8 * t + (l >> 2);
    int k0 = 16 * s + 2 * (l & 3);

    float w0 = src[(k0 + 0) * 128 + n];
    float w1 = src[(k0 + 1) * 128 + n];
    float w8 = src[(k0 + 8) * 128 + n];
    float w9 = src[(k0 + 9) * 128 + n];
    uint4 o;
    split2(w0, w1, o.x, o.z);
    split2(w8, w9, o.y, o.w);
    g_wfrag[(size_t)slot * 4096 + q] = o;
}

// Wg prepass: [5][K=64][F=128] -> per-lane fragments. grid (16, 5), block 128
__global__ void wgfrag_k(const float* __restrict__ Wg)
{
    int slot = blockIdx.y;
    const float* src = Wg + (size_t)slot * KDIM * FDIM;
    int q = blockIdx.x * 128 + threadIdx.x;   // 0..2047
    int l = q & 31, t = (q >> 5) & 15, s = q >> 9;   // s 0..3
    int n = 8 * t + (l >> 2);
    int k0 = 16 * s + 2 * (l & 3);
    float w0 = src[(k0 + 0) * 128 + n];
    float w1 = src[(k0 + 1) * 128 + n];
    float w8 = src[(k0 + 8) * 128 + n];
    float w9 = src[(k0 + 9) * 128 + n];
    uint4 o;
    split2(w0, w1, o.x, o.z);
    split2(w8, w9, o.y, o.w);
    g_gfrag[(size_t)slot * 2048 + q] = o;
}

// ---------------------------------------------------------------------------
// Tensor-core GEMM: Y = epi( pre(X) @ W + bias ; R, U )
//   PRE=1: ssp on load.  EPI=0: ssp(z)  EPI=2: U[col]*R + z
// ---------------------------------------------------------------------------
template <int PRE, int EPI>
__global__ __launch_bounds__(128, 2)
void tmma_k(const float* __restrict__ X, const uint4* __restrict__ WF,
            const float* __restrict__ bias, const float* __restrict__ R,
            const float* __restrict__ U, float* __restrict__ Y, int M)
{
    const int tid = threadIdx.x;
    const int w = tid >> 5, l = tid & 31;
    const int c = l & 3, g = l >> 2;
    const int r0 = blockIdx.x * 64 + w * 16 + g;
    const int r1 = r0 + 8;
    const float* xr0 = X + (size_t)min(r0, M - 1) * FDIM;
    const float* xr1 = X + (size_t)min(r1, M - 1) * FDIM;

    uint32_t ahi[8][4], alo[8][4];
#pragma unroll
    for (int s = 0; s < 8; s++) {
        int col0 = 16 * s + 2 * c;
        float2 v00 = *(const float2*)(xr0 + col0);
        float2 v10 = *(const float2*)(xr1 + col0);
        float2 v01 = *(const float2*)(xr0 + col0 + 8);
        float2 v11 = *(const float2*)(xr1 + col0 + 8);
        if (PRE) {
            v00.x = sspf(v00.x); v00.y = sspf(v00.y);
            v10.x = sspf(v10.x); v10.y = sspf(v10.y);
            v01.x = sspf(v01.x); v01.y = sspf(v01.y);
            v11.x = sspf(v11.x); v11.y = sspf(v11.y);
        }
        split2(v00.x, v00.y, ahi[s][0], alo[s][0]);
        split2(v10.x, v10.y, ahi[s][1], alo[s][1]);
        split2(v01.x, v01.y, ahi[s][2], alo[s][2]);
        split2(v11.x, v11.y, ahi[s][3], alo[s][3]);
    }

    const bool ok0 = (r0 < M), ok1 = (r1 < M);

#pragma unroll
    for (int t = 0; t < 16; t++) {
        float d0 = 0.f, d1 = 0.f, d2 = 0.f, d3 = 0.f;
#pragma unroll
        for (int s = 0; s < 8; s++) {
            uint4 b = WF[(size_t)((s * 16 + t) * 32 + l)];
            MMA3(d0, d1, d2, d3, ahi[s], alo[s], b);
        }
        const int col = 8 * t + 2 * c;
        float2 bv = *(const float2*)(bias + col);
        d0 += bv.x; d1 += bv.y; d2 += bv.x; d3 += bv.y;

        float2 o0, o1;
        if (EPI == 0) {
            o0.x = sspf(d0); o0.y = sspf(d1);
            o1.x = sspf(d2); o1.y = sspf(d3);
        } else {
            float2 uv = *(const float2*)(U + col);
            float2 rv0 = ok0 ? *(const float2*)(R + (size_t)r0 * FDIM + col) : make_float2(0.f, 0.f);
            float2 rv1 = ok1 ? *(const float2*)(R + (size_t)r1 * FDIM + col) : make_float2(0.f, 0.f);
            o0.x = fmaf(uv.x, rv0.x, d0); o0.y = fmaf(uv.y, rv0.y, d1);
            o1.x = fmaf(uv.x, rv1.x, d2); o1.y = fmaf(uv.y, rv1.y, d3);
        }
        if (ok0) *(float2*)(Y + (size_t)r0 * FDIM + col) = o0;
        if (ok1) *(float2*)(Y + (size_t)r1 * FDIM + col) = o1;
    }
}

// ---------------------------------------------------------------------------
// Fused residual layer: Y = X + ssp(ssp(X)@W1+b1)@W2 + b2   (Y may alias X)
// GEMM1 accumulator fragments feed GEMM2 A-fragments entirely in registers:
// n-tile 2s -> (a0,a1), n-tile 2s+1 -> (a2,a3).
// ---------------------------------------------------------------------------
__global__ __launch_bounds__(128, 2)
void rsd_k(const float* __restrict__ X,
           const uint4* __restrict__ WF1, const float* __restrict__ b1,
           const uint4* __restrict__ WF2, const float* __restrict__ b2,
           float* __restrict__ Y, int M)
{
    const int tid = threadIdx.x;
    const int w = tid >> 5, l = tid & 31;
    const int c = l & 3, g = l >> 2;
    const int r0 = blockIdx.x * 64 + w * 16 + g;
    const int r1 = r0 + 8;
    const float* xr0 = X + (size_t)min(r0, M - 1) * FDIM;
    const float* xr1 = X + (size_t)min(r1, M - 1) * FDIM;

    uint32_t ahi[8][4], alo[8][4];
#pragma unroll
    for (int s = 0; s < 8; s++) {
        int col0 = 16 * s + 2 * c;
        float2 v00 = *(const float2*)(xr0 + col0);
        float2 v10 = *(const float2*)(xr1 + col0);
        float2 v01 = *(const float2*)(xr0 + col0 + 8);
        float2 v11 = *(const float2*)(xr1 + col0 + 8);
        v00.x = sspf(v00.x); v00.y = sspf(v00.y);
        v10.x = sspf(v10.x); v10.y = sspf(v10.y);
        v01.x = sspf(v01.x); v01.y = sspf(v01.y);
        v11.x = sspf(v11.x); v11.y = sspf(v11.y);
        split2(v00.x, v00.y, ahi[s][0], alo[s][0]);
        split2(v10.x, v10.y, ahi[s][1], alo[s][1]);
        split2(v01.x, v01.y, ahi[s][2], alo[s][2]);
        split2(v11.x, v11.y, ahi[s][3], alo[s][3]);
    }

    // GEMM1: z[t][4] over all 16 n-tiles, ssp applied
    float z[16][4];
#pragma unroll
    for (int t = 0; t < 16; t++) {
        float d0 = 0.f, d1 = 0.f, d2 = 0.f, d3 = 0.f;
#pragma unroll
        for (int s = 0; s < 8; s++) {
            uint4 b = WF1[(size_t)((s * 16 + t) * 32 + l)];
            MMA3(d0, d1, d2, d3, ahi[s], alo[s], b);
        }
        const int col = 8 * t + 2 * c;
        float2 bv = *(const float2*)(b1 + col);
        z[t][0] = sspf(d0 + bv.x); z[t][1] = sspf(d1 + bv.y);
        z[t][2] = sspf(d2 + bv.x); z[t][3] = sspf(d3 + bv.y);
    }

    // Repack z into A-fragments for GEMM2 (register-resident, no shuffle)
#pragma unroll
    for (int s = 0; s < 8; s++) {
        split2(z[2 * s][0],     z[2 * s][1],     ahi[s][0], alo[s][0]);
        split2(z[2 * s][2],     z[2 * s][3],     ahi[s][1], alo[s][1]);
        split2(z[2 * s + 1][0], z[2 * s + 1][1], ahi[s][2], alo[s][2]);
        split2(z[2 * s + 1][2], z[2 * s + 1][3], ahi[s][3], alo[s][3]);
    }

    const bool ok0 = (r0 < M), ok1 = (r1 < M);

    // GEMM2 + residual epilogue
#pragma unroll
    for (int t = 0; t < 16; t++) {
        float d0 = 0.f, d1 = 0.f, d2 = 0.f, d3 = 0.f;
#pragma unroll
        for (int s = 0; s < 8; s++) {
            uint4 b = WF2[(size_t)((s * 16 + t) * 32 + l)];
            MMA3(d0, d1, d2, d3, ahi[s], alo[s], b);
        }
        const int col = 8 * t + 2 * c;
        float2 bv = *(const float2*)(b2 + col);
        float2 rv0 = ok0 ? *(const float2*)(X + (size_t)r0 * FDIM + col) : make_float2(0.f, 0.f);
        float2 rv1 = ok1 ? *(const float2*)(X + (size_t)r1 * FDIM + col) : make_float2(0.f, 0.f);
        float2 o0, o1;
        o0.x = rv0.x + d0 + bv.x; o0.y = rv0.y + d1 + bv.y;
        o1.x = rv1.x + d2 + bv.x; o1.y = rv1.y + d3 + bv.y;
        if (ok0) *(float2*)(Y + (size_t)r0 * FDIM + col) = o0;
        if (ok1) *(float2*)(Y + (size_t)r1 * FDIM + col) = o1;
    }
}

// ---------------------------------------------------------------------------
// Fused xi/xj GEMM: shared ssp+split A-fragments, two weight sets / outputs.
// ---------------------------------------------------------------------------
__global__ __launch_bounds__(128, 2)
void tmma2_k(const float* __restrict__ X,
             const uint4* __restrict__ WF1, const float* __restrict__ b1, float* __restrict__ Y1,
             const uint4* __restrict__ WF2, const float* __restrict__ b2, float* __restrict__ Y2,
             int M)
{
    const int tid = threadIdx.x;
    const int w = tid >> 5, l = tid & 31;
    const int c = l & 3, g = l >> 2;
    const int r0 = blockIdx.x * 64 + w * 16 + g;
    const int r1 = r0 + 8;
    const float* xr0 = X + (size_t)min(r0, M - 1) * FDIM;
    const float* xr1 = X + (size_t)min(r1, M - 1) * FDIM;

    uint32_t ahi[8][4], alo[8][4];
#pragma unroll
    for (int s = 0; s < 8; s++) {
        int col0 = 16 * s + 2 * c;
        float2 v00 = *(const float2*)(xr0 + col0);
        float2 v10 = *(const float2*)(xr1 + col0);
        float2 v01 = *(const float2*)(xr0 + col0 + 8);
        float2 v11 = *(const float2*)(xr1 + col0 + 8);
        v00.x = sspf(v00.x); v00.y = sspf(v00.y);
        v10.x = sspf(v10.x); v10.y = sspf(v10.y);
        v01.x = sspf(v01.x); v01.y = sspf(v01.y);
        v11.x = sspf(v11.x); v11.y = sspf(v11.y);
        split2(v00.x, v00.y, ahi[s][0], alo[s][0]);
        split2(v10.x, v10.y, ahi[s][1], alo[s][1]);
        split2(v01.x, v01.y, ahi[s][2], alo[s][2]);
        split2(v11.x, v11.y, ahi[s][3], alo[s][3]);
    }

    const bool ok0 = (r0 < M), ok1 = (r1 < M);

#pragma unroll
    for (int m = 0; m < 2; m++) {
        const uint4* WF = m ? WF2 : WF1;
        const float* bias = m ? b2 : b1;
        float* Y = m ? Y2 : Y1;
#pragma unroll
        for (int t = 0; t < 16; t++) {
            float d0 = 0.f, d1 = 0.f, d2 = 0.f, d3 = 0.f;
#pragma unroll
            for (int s = 0; s < 8; s++) {
                uint4 b = WF[(size_t)((s * 16 + t) * 32 + l)];
                MMA3(d0, d1, d2, d3, ahi[s], alo[s], b);
            }
            const int col = 8 * t + 2 * c;
            float2 bv = *(const float2*)(bias + col);
            float2 o0, o1;
            o0.x = sspf(d0 + bv.x); o0.y = sspf(d1 + bv.y);
            o1.x = sspf(d2 + bv.x); o1.y = sspf(d3 + bv.y);
            if (ok0) *(float2*)(Y + (size_t)r0 * FDIM + col) = o0;
            if (ok1) *(float2*)(Y + (size_t)r1 * FDIM + col) = o1;
        }
    }
}

// ---------------------------------------------------------------------------
// Fused message pass, tensor-core filter, 32-pair chunks.
// ---------------------------------------------------------------------------
#define MSG_T 128
#define MSG_PPB 512
#define DESC_P 68
#define GSM_P 132

__global__ __launch_bounds__(MSG_T)
void msgmma_k(const float* __restrict__ cutoffs, const float* __restrict__ rbfs,
              const int* __restrict__ idx_i, const int* __restrict__ idx_j,
              const uint4* __restrict__ GF, const float* __restrict__ xj,
              float* __restrict__ m, int npairs)
{
    __shared__ __align__(16) float desc[32][DESC_P];
    __shared__ __align__(16) float gsm[32][GSM_P];
    __shared__ int si[32], sj[32];

    const int t = threadIdx.x;
    const int w = t >> 5, l = t & 31;
    const int c = l & 3, g = l >> 2;

    const int p0 = blockIdx.x * MSG_PPB;
    const int pend = min(p0 + MSG_PPB, npairs);

    float acc = 0.0f;
    int prev = -1;

    for (int base = p0; base < pend; base += 32) {
        const int ns = min(32, pend - base);
        __syncthreads();   // prev chunk phase-c done with gsm/si/sj
        // ---- stage desc = cutoff * rbf (32 rows x 16 float4) ----
        for (int li = t; li < ns * 16; li += MSG_T) {
            int s = li >> 4, v = li & 15;
            float cf = cutoffs[base + s];
            float4 r = *(const float4*)&rbfs[(size_t)(base + s) * KDIM + v * 4];
            r.x *= cf; r.y *= cf; r.z *= cf; r.w *= cf;
            *(float4*)&desc[s][v * 4] = r;
        }
        if (t < ns) { si[t] = idx_i[base + t]; sj[t] = idx_j[base + t]; }
        __syncthreads();

        // ---- g tile via MMA: 2 m-tiles (rows 0-15, 16-31), warp w: n-tiles 4w..4w+3
        uint32_t ahi[2][4][4], alo[2][4][4];
#pragma unroll
        for (int mt = 0; mt < 2; mt++) {
            int rg = mt * 16 + g;
#pragma unroll
            for (int s = 0; s < 4; s++) {
                int k0 = 16 * s + 2 * c;
                float2 v00 = *(const float2*)&desc[rg][k0];
                float2 v10 = *(const float2*)&desc[rg + 8][k0];
                float2 v01 = *(const float2*)&desc[rg][k0 + 8];
                float2 v11 = *(const float2*)&desc[rg + 8][k0 + 8];
                split2(v00.x, v00.y, ahi[mt][s][0], alo[mt][s][0]);
                split2(v10.x, v10.y, ahi[mt][s][1], alo[mt][s][1]);
                split2(v01.x, v01.y, ahi[mt][s][2], alo[mt][s][2]);
                split2(v11.x, v11.y, ahi[mt][s][3], alo[mt][s][3]);
            }
        }
#pragma unroll
        for (int j = 0; j < 4; j++) {
            const int tt = 4 * w + j;
            const int col = 8 * tt + 2 * c;
#pragma unroll
            for (int mt = 0; mt < 2; mt++) {
                float d0 = 0.f, d1 = 0.f, d2 = 0.f, d3 = 0.f;
#pragma unroll
                for (int s = 0; s < 4; s++) {
                    uint4 b = GF[(size_t)((s * 16 + tt) * 32 + l)];
                    MMA3(d0, d1, d2, d3, ahi[mt][s], alo[mt][s], b);
                }
                int rg = mt * 16 + g;
                *(float2*)&gsm[rg][col] = make_float2(d0, d1);
                *(float2*)&gsm[rg + 8][col] = make_float2(d2, d3);
            }
        }
        __syncthreads();

        // ---- per-feature segment accumulate ----
        for (int s = 0; s < ns; s++) {
            int i = si[s], j = sj[s];
            if (i != prev) {
                if (prev >= 0) atomicAdd(&m[(size_t)prev * FDIM + t], acc);
                acc = 0.0f;
                prev = i;
            }
            acc = fmaf(gsm[s][t], xj[(size_t)j * FDIM + t], acc);
        }
    }
    if (prev >= 0) atomicAdd(&m[(size_t)prev * FDIM + t], acc);
}

// ---------------------------------------------------------------------------
extern "C" void kernel_launch(void* const* d_in, const int* in_sizes, int n_in,
                              void* d_out, int out_size)
{
    const float* features = (const float*)d_in[0];
    const float* cutoffs  = (const float*)d_in[1];
    const float* rbfs     = (const float*)d_in[2];
    const int*   idx_i    = (const int*)d_in[3];
    const int*   idx_j    = (const int*)d_in[4];
    const float* Wg   = (const float*)d_in[5];
    const float* bi   = (const float*)d_in[7];
    const float* bj   = (const float*)d_in[9];
    const float* br1  = (const float*)d_in[11];
    const float* br2  = (const float*)d_in[13];
    const float* bout = (const float*)d_in[15];
    const float* u    = (const float*)d_in[16];
    const float* bf1  = (const float*)d_in[18];
    const float* bf2  = (const float*)d_in[20];
    const int npairs = in_sizes[1];
    float* out = (float*)d_out;

    float *xjp, *mp;
    uint4 *wfrag, *gfrag;
    cudaGetSymbolAddress((void**)&xjp, g_xj);
    cudaGetSymbolAddress((void**)&mp,  g_m);
    cudaGetSymbolAddress((void**)&wfrag, g_wfrag);
    cudaGetSymbolAddress((void**)&gfrag, g_gfrag);

    const int gemmGrid = (NATOMS + 63) / 64;
    const int msgGrid = (npairs + MSG_PPB - 1) / MSG_PPB;

    // prepasses (cheap; once per launch)
    wfrag_k<<<dim3(32, NWMAT), 128>>>((const float*)d_in[6], (const float*)d_in[8],
                                      (const float*)d_in[10], (const float*)d_in[12],
                                      (const float*)d_in[14], (const float*)d_in[17],
                                      (const float*)d_in[19]);
    wgfrag_k<<<dim3(16, NB), 128>>>(Wg);

    auto WFr = [&](int slot) { return wfrag + (size_t)slot * 4096; };

    const float* x = features;
    for (int b = 0; b < NB; b++) {
        float* xout = out + (size_t)b * NATOMS * FDIM;

        // m = xi = ssp(ssp(x)@Wi+bi);  xj = ssp(ssp(x)@Wj+bj)   (fused)
        tmma2_k<<<gemmGrid, 128>>>(x, WFr(b), bi + b * FDIM, mp,
                                   WFr(5 + b), bj + b * FDIM, xjp, NATOMS);
        // m += segment_sum( (desc @ Wg) * xj[idx_j], idx_i )
        msgmma_k<<<msgGrid, MSG_T>>>(cutoffs, rbfs, idx_i, idx_j,
                                     gfrag + (size_t)b * 2048, xjp, mp, npairs);
        // interaction residuals (fused pairs, in-place)
        for (int r = 0; r < NRI; r++) {
            int s1 = 10 + b * NRI + r, s2 = 25 + b * NRI + r;
            rsd_k<<<gemmGrid, 128>>>(mp, WFr(s1), br1 + (size_t)(b * NRI + r) * FDIM,
                                     WFr(s2), br2 + (size_t)(b * NRI + r) * FDIM, mp, NATOMS);
        }
        // x' = u*x + ssp(m) @ Wout + bout
        tmma_k<1, 2><<<gemmGrid, 128>>>(mp, WFr(40 + b), bout + b * FDIM,
                                        x, u + b * FDIM, xout, NATOMS);
        // feature residuals (fused pairs, in-place on output slab)
        for (int r = 0; r < NRF; r++) {
            int s1 = 45 + b * NRF + r, s2 = 55 + b * NRF + r;
            rsd_k<<<gemmGrid, 128>>>(xout, WFr(s1), bf1 + (size_t)(b * NRF + r) * FDIM,
                                     WFr(s2), bf2 + (size_t)(b * NRF + r) * FDIM, xout, NATOMS);
        }
        x = xout;
    }
}